// round 13
// baseline (speedup 1.0000x reference)
#include <cuda_runtime.h>
#include <cuda_fp16.h>
#include <cuda_fp8.h>
#include <cstdint>

#define N_NODES 100000
#define E_EDGES 3200000
#define HIDF    128
#define GG      64
#define BN_EPS  1e-5f
#define NB_SCAN 391   // ceil(N_NODES/256)
#define TSCALE  16.0f
#define INV_TSCALE (1.0f / 16.0f)
#define POOL_SPLIT 8

// ---------------- static device scratch (no runtime allocations) -------------
__device__ int   g_is64;
__device__ float g_dis[N_NODES];
__device__ int   g_hist[N_NODES];
__device__ int   g_off[N_NODES];
__device__ int   g_cursor[N_NODES];
__device__ int   g_bsum[512];
__device__ int   g_sidx[E_EDGES];
__device__ __align__(16) unsigned g_xf8[((size_t)N_NODES + 1) * 32]; // fp8 table + zero dummy row
__device__ __align__(16) __half g_hbuf[3u * N_NODES * HIDF];
__device__ __align__(16) __half g_Wh[3 * 2 * 64 * 64];
__device__ __align__(16) float g_bp[3 * HIDF];
__device__ float g_pooled[GG * 3 * HIDF];
__device__ int   g_cnt[GG];
__device__ int   g_start[GG];

static __device__ __forceinline__ __half2 fp8x2_to_h2(unsigned short v) {
    __half2_raw hr = __nv_cvt_fp8x2_to_halfraw2((__nv_fp8x2_storage_t)v, __NV_E4M3);
    return *reinterpret_cast<__half2*>(&hr);
}
static __device__ __forceinline__ unsigned short f2_to_fp8x2(float a, float b) {
    return (unsigned short)__nv_cvt_float2_to_fp8x2(make_float2(a, b), __NV_SATFINITE, __NV_E4M3);
}

// ---------------- init + dtype detect + zeroing + BN fold --------------------
__global__ void k_init(const int* __restrict__ ei32,
                       const float* __restrict__ W, const float* __restrict__ b,
                       const float* __restrict__ gamma, const float* __restrict__ beta,
                       const float* __restrict__ mean, const float* __restrict__ var) {
    int i = blockIdx.x * blockDim.x + threadIdx.x;
    if (i < N_NODES) g_hist[i] = 0;
    if (i < GG) { g_cnt[i] = 0; g_start[i] = 0; }
    if (i < GG * 3 * HIDF) g_pooled[i] = 0.f;
    if (i < 32) g_xf8[(size_t)N_NODES * 32 + i] = 0u;   // dummy zero row
    if (i == 0) {
        int odd_zero = 1;
        for (int k = 0; k < 64; k++)
            if (ei32[2 * k + 1] != 0) odd_zero = 0;
        g_is64 = odd_zero;
    }
    if (i < 3 * 8192) {
        int l = i / 8192;
        int rem = i - l * 8192;
        int p = rem / 4096;
        int j = rem & 63;
        int c = p * 64 + j;
        float sg = gamma[l * HIDF + c] * rsqrtf(var[l * HIDF + c] + BN_EPS);
        g_Wh[i] = __float2half(W[i] * sg);
    }
    if (i < 3 * HIDF) {
        float sg = gamma[i] * rsqrtf(var[i] + BN_EPS);
        g_bp[i] = b[i] * sg + (beta[i] - mean[i] * sg);
    }
}

// histogram over destination
__global__ void k_edge(const void* __restrict__ eiv) {
    int e = blockIdx.x * blockDim.x + threadIdx.x;
    if (e >= E_EDGES) return;
    int c;
    if (g_is64) c = (int)((const long long*)eiv)[(size_t)E_EDGES + e];
    else        c = ((const int*)eiv)[E_EDGES + e];
    atomicAdd(&g_hist[c], 1);
}

// ---------------- scan level 1 (+ dis = rsqrt(deg+1)) ------------------------
__global__ void __launch_bounds__(256) k_scan1() {
    __shared__ int sh[256];
    int bidx = blockIdx.x, t = threadIdx.x;
    int i = bidx * 256 + t;
    int v = (i < N_NODES) ? g_hist[i] : 0;
    if (i < N_NODES) g_dis[i] = rsqrtf((float)(v + 1));
    sh[t] = v;
    __syncthreads();
    for (int o = 1; o < 256; o <<= 1) {
        int u = (t >= o) ? sh[t - o] : 0;
        __syncthreads();
        sh[t] += u;
        __syncthreads();
    }
    if (i < N_NODES) g_off[i] = sh[t] - v;
    if (t == 255) g_bsum[bidx] = sh[255];
}

// ---------------- scan level 2+3 fused: per-block prefix of bsum -------------
__global__ void __launch_bounds__(256) k_scan3() {
    __shared__ int sh[256];
    int bidx = blockIdx.x, t = threadIdx.x;
    int part = 0;
    for (int k = t; k < NB_SCAN; k += 256)
        if (k < bidx) part += g_bsum[k];
    sh[t] = part;
    __syncthreads();
    for (int o = 128; o > 0; o >>= 1) {
        if (t < o) sh[t] += sh[t + o];
        __syncthreads();
    }
    int boff = sh[0];
    int i = bidx * 256 + t;
    if (i < N_NODES) {
        int o = g_off[i] + boff;
        g_off[i] = o;
        g_cursor[i] = o;
    }
}

// place src index into dest-sorted order (+ batch segment bookkeeping)
__global__ void k_place(const void* __restrict__ eiv, const void* __restrict__ bv) {
    int e = blockIdx.x * blockDim.x + threadIdx.x;
    if (e < N_NODES) {
        int b, bp = -1;
        if (g_is64) {
            const long long* bb = (const long long*)bv;
            b = (int)bb[e];
            if (e > 0) bp = (int)bb[e - 1];
        } else {
            const int* bb = (const int*)bv;
            b = bb[e];
            if (e > 0) bp = bb[e - 1];
        }
        atomicAdd(&g_cnt[b], 1);
        if (e == 0 || bp != b) g_start[b] = e;
    }
    if (e >= E_EDGES) return;
    int r, c;
    if (g_is64) {
        const long long* ei = (const long long*)eiv;
        r = (int)ei[e];
        c = (int)ei[(size_t)E_EDGES + e];
    } else {
        const int* ei = (const int*)eiv;
        r = ei[e];
        c = ei[E_EDGES + e];
    }
    int pos = atomicAdd(&g_cursor[c], 1);
    g_sidx[pos] = r;
}

// ---------------- tensor-core block-diagonal GEMM -> fp8 table ---------------
#define SA_LD 136
#define SB_LD 72
__global__ void __launch_bounds__(256) k_gemm(const float* __restrict__ x,
                                              int src_layer, int layer) {
    __shared__ __half sA[64 * SA_LD];
    __shared__ __half sB[2 * 64 * SB_LD];
    int t = threadIdx.x;
    int R0 = blockIdx.x * 64;

    const __half* Wl = g_Wh + layer * 8192;
    for (int i = t; i < 8192; i += 256) {
        int p = i >> 12, k = (i >> 6) & 63, j = i & 63;
        sB[(p * 64 + k) * SB_LD + j] = Wl[i];
    }
    if (src_layer < 0) {
        for (int i = t; i < 2048; i += 256) {
            int r = i >> 5, c4 = i & 31;
            float4 v = make_float4(0.f, 0.f, 0.f, 0.f);
            if (R0 + r < N_NODES) v = ((const float4*)x)[(size_t)(R0 + r) * 32 + c4];
            __half* dst = sA + r * SA_LD + c4 * 4;
            dst[0] = __float2half(v.x); dst[1] = __float2half(v.y);
            dst[2] = __float2half(v.z); dst[3] = __float2half(v.w);
        }
    } else {
        const uint2* hb = reinterpret_cast<const uint2*>(
            g_hbuf + (size_t)src_layer * N_NODES * HIDF);
        const __half2 z2 = __floats2half2_rn(0.f, 0.f);
        for (int i = t; i < 2048; i += 256) {
            int r = i >> 5, c4 = i & 31;
            __half2 h0 = z2, h1 = z2;
            if (R0 + r < N_NODES) {
                uint2 hw = hb[(size_t)(R0 + r) * 32 + c4];
                h0 = __hmax2(*reinterpret_cast<__half2*>(&hw.x), z2);
                h1 = __hmax2(*reinterpret_cast<__half2*>(&hw.y), z2);
            }
            __half* dst = sA + r * SA_LD + c4 * 4;
            *reinterpret_cast<__half2*>(dst) = h0;
            *reinterpret_cast<__half2*>(dst + 2) = h1;
        }
    }
    __syncthreads();

    int w = t >> 5, lane = t & 31;
    int part = w & 1;
    int wr = (w >> 1) << 4;
    int g = lane >> 2, tig = lane & 3;

    float d[8][4];
#pragma unroll
    for (int n = 0; n < 8; n++) { d[n][0] = d[n][1] = d[n][2] = d[n][3] = 0.f; }

    int mrow = lane & 7;
    int msel = lane >> 3;
    int arow = wr + mrow + ((msel & 1) << 3);
    int acolb = part * 64 + ((msel >> 1) << 3);
    int brow_l = lane & 15;

#pragma unroll
    for (int kt = 0; kt < 4; kt++) {
        uint32_t a0, a1, a2, a3;
        uint32_t aaddr = (uint32_t)__cvta_generic_to_shared(
            sA + arow * SA_LD + acolb + kt * 16);
        asm volatile("ldmatrix.sync.aligned.m8n8.x4.shared.b16 {%0,%1,%2,%3}, [%4];"
                     : "=r"(a0), "=r"(a1), "=r"(a2), "=r"(a3) : "r"(aaddr));
#pragma unroll
        for (int nt = 0; nt < 8; nt++) {
            uint32_t b0, b1;
            uint32_t baddr = (uint32_t)__cvta_generic_to_shared(
                sB + (part * 64 + kt * 16 + brow_l) * SB_LD + nt * 8);
            asm volatile("ldmatrix.sync.aligned.m8n8.x2.trans.shared.b16 {%0,%1}, [%2];"
                         : "=r"(b0), "=r"(b1) : "r"(baddr));
            asm volatile("mma.sync.aligned.m16n8k16.row.col.f32.f16.f16.f32 "
                         "{%0,%1,%2,%3}, {%4,%5,%6,%7}, {%8,%9}, {%0,%1,%2,%3};"
                         : "+f"(d[nt][0]), "+f"(d[nt][1]), "+f"(d[nt][2]), "+f"(d[nt][3])
                         : "r"(a0), "r"(a1), "r"(a2), "r"(a3), "r"(b0), "r"(b1));
        }
    }

    int row0 = R0 + wr + g;
    int row1 = row0 + 8;
    unsigned short* xf16 = reinterpret_cast<unsigned short*>(g_xf8);
    if (row0 < N_NODES) {
        float sc = TSCALE * g_dis[row0];
#pragma unroll
        for (int nt = 0; nt < 8; nt++) {
            int cidx = part * 32 + nt * 4 + tig;
            xf16[(size_t)row0 * 64 + cidx] = f2_to_fp8x2(d[nt][0] * sc, d[nt][1] * sc);
        }
    }
    if (row1 < N_NODES) {
        float sc = TSCALE * g_dis[row1];
#pragma unroll
        for (int nt = 0; nt < 8; nt++) {
            int cidx = part * 32 + nt * 4 + tig;
            xf16[(size_t)row1 * 64 + cidx] = f2_to_fp8x2(d[nt][2] * sc, d[nt][3] * sc);
        }
    }
}

// ---------------- segmented sum: one warp per node, 4 edges/iter -------------
// Quarter-warp q handles edges 4j+q; lane loads uint4 (16B) of the 128B row.
// Out-of-range lanes use the zero dummy row N_NODES.
__global__ void __launch_bounds__(256) k_aggr(int layer) {
    int node = (blockIdx.x * 256 + threadIdx.x) >> 5;
    if (node >= N_NODES) return;
    int lane = threadIdx.x & 31;
    int lg = lane & 7;                // lane within quarter (feature slice)
    int q = lane >> 3;                // quarter 0..3
    int s0 = g_off[node];
    int s1 = (node + 1 < N_NODES) ? g_off[node + 1] : E_EDGES;

    const uint4* __restrict__ xb4 = reinterpret_cast<const uint4*>(g_xf8);
    const __half2 z2 = __floats2half2_rn(0.f, 0.f);
    __half2 acc[8];
#pragma unroll
    for (int k = 0; k < 8; k++) acc[k] = z2;

    for (int s = s0; s < s1; s += 32) {
        int idx = N_NODES;                       // zero dummy row
        if (s + lane < s1) idx = g_sidx[s + lane];
        int cnt = min(32, s1 - s);
        int jmax = (cnt + 3) >> 2;
        for (int j = 0; j < jmax; j++) {
            int r = __shfl_sync(0xffffffffu, idx, 4 * j + q);
            uint4 w = __ldg(xb4 + (size_t)r * 8 + lg);
            acc[0] = __hadd2(acc[0], fp8x2_to_h2((unsigned short)(w.x & 0xffffu)));
            acc[1] = __hadd2(acc[1], fp8x2_to_h2((unsigned short)(w.x >> 16)));
            acc[2] = __hadd2(acc[2], fp8x2_to_h2((unsigned short)(w.y & 0xffffu)));
            acc[3] = __hadd2(acc[3], fp8x2_to_h2((unsigned short)(w.y >> 16)));
            acc[4] = __hadd2(acc[4], fp8x2_to_h2((unsigned short)(w.z & 0xffffu)));
            acc[5] = __hadd2(acc[5], fp8x2_to_h2((unsigned short)(w.z >> 16)));
            acc[6] = __hadd2(acc[6], fp8x2_to_h2((unsigned short)(w.w & 0xffffu)));
            acc[7] = __hadd2(acc[7], fp8x2_to_h2((unsigned short)(w.w >> 16)));
        }
    }

    // combine quarters (same lg across q)
#pragma unroll
    for (int k = 0; k < 8; k++) {
        acc[k] = __hadd2(acc[k], __shfl_xor_sync(0xffffffffu, acc[k], 8));
        acc[k] = __hadd2(acc[k], __shfl_xor_sync(0xffffffffu, acc[k], 16));
    }

    if (q == 0) {
        // add self row (self-loop), then scale + bias, store fp16 row chunk
        uint4 sw = xb4[(size_t)node * 8 + lg];
        acc[0] = __hadd2(acc[0], fp8x2_to_h2((unsigned short)(sw.x & 0xffffu)));
        acc[1] = __hadd2(acc[1], fp8x2_to_h2((unsigned short)(sw.x >> 16)));
        acc[2] = __hadd2(acc[2], fp8x2_to_h2((unsigned short)(sw.y & 0xffffu)));
        acc[3] = __hadd2(acc[3], fp8x2_to_h2((unsigned short)(sw.y >> 16)));
        acc[4] = __hadd2(acc[4], fp8x2_to_h2((unsigned short)(sw.z & 0xffffu)));
        acc[5] = __hadd2(acc[5], fp8x2_to_h2((unsigned short)(sw.z >> 16)));
        acc[6] = __hadd2(acc[6], fp8x2_to_h2((unsigned short)(sw.w & 0xffffu)));
        acc[7] = __hadd2(acc[7], fp8x2_to_h2((unsigned short)(sw.w >> 16)));

        float dcs = g_dis[node] * INV_TSCALE;
        const float4* bp4 = (const float4*)g_bp;
        uint4 st0, st1;
        unsigned* stp = &st0.x;
#pragma unroll
        for (int k = 0; k < 8; k++) {
            float4 bb = bp4[layer * 32 + lg * 4 + k / 2];
            float2 f = __half22float2(acc[k]);
            float ox = ((k & 1) ? bb.z : bb.x) + f.x * dcs;
            float oy = ((k & 1) ? bb.w : bb.y) + f.y * dcs;
            __half2 o = __floats2half2_rn(ox, oy);
            if (k < 4) stp[k] = *reinterpret_cast<unsigned*>(&o);
            else       (&st1.x)[k - 4] = *reinterpret_cast<unsigned*>(&o);
        }
        uint4* dst = reinterpret_cast<uint4*>(g_hbuf + (size_t)layer * N_NODES * HIDF)
                   + (size_t)node * 16;
        dst[lg * 2] = st0;
        dst[lg * 2 + 1] = st1;
    }
}

// ---------------- mean pool: split + atomic partial sums ---------------------
__global__ void __launch_bounds__(128) k_pool() {
    int g = blockIdx.x;
    int l = blockIdx.y;
    int z = blockIdx.z;
    int t = threadIdx.x;
    int s = g_start[g];
    int n = g_cnt[g];
    int chunk = (n + POOL_SPLIT - 1) / POOL_SPLIT;
    int j0 = z * chunk;
    int j1 = min(n, j0 + chunk);
    if (j0 >= j1) return;
    const __half* base = g_hbuf + ((size_t)l * N_NODES + s) * HIDF + t;
    float acc = 0.f;
    for (int j = j0; j < j1; j++) acc += fmaxf(__half2float(base[(size_t)j * HIDF]), 0.f);
    atomicAdd(&g_pooled[g * (3 * HIDF) + l * HIDF + t], acc);
}

// ---------------- MLP head + log_softmax (divides pooled by count) -----------
__global__ void __launch_bounds__(128) k_head(const float* __restrict__ Wfc1,
                                              const float* __restrict__ bfc1,
                                              const float* __restrict__ Wfc2,
                                              const float* __restrict__ bfc2,
                                              float* __restrict__ out) {
    __shared__ float sP[3 * HIDF];
    __shared__ float sH[HIDF];
    __shared__ float sZ[2];
    int g = blockIdx.x;
    int t = threadIdx.x;
    float inv = 1.0f / fmaxf((float)g_cnt[g], 1.0f);
    for (int i = t; i < 3 * HIDF; i += 128) sP[i] = g_pooled[g * (3 * HIDF) + i] * inv;
    __syncthreads();
    float acc = bfc1[t];
#pragma unroll 8
    for (int k = 0; k < 3 * HIDF; k++) acc += sP[k] * Wfc1[k * HIDF + t];
    sH[t] = fmaxf(acc, 0.f);
    __syncthreads();
    if (t < 2) {
        float z = bfc2[t];
#pragma unroll 8
        for (int j = 0; j < HIDF; j++) z += sH[j] * Wfc2[j * 2 + t];
        sZ[t] = z;
    }
    __syncthreads();
    if (t == 0) {
        float z0 = sZ[0], z1 = sZ[1];
        float m = fmaxf(z0, z1);
        float lse = m + logf(expf(z0 - m) + expf(z1 - m));
        out[g * 2 + 0] = z0 - lse;
        out[g * 2 + 1] = z1 - lse;
    }
}

// ---------------- driver ------------------------------------------------------
extern "C" void kernel_launch(void* const* d_in, const int* in_sizes, int n_in,
                              void* d_out, int out_size) {
    const float* x        = (const float*)d_in[0];
    const void*  ei       = d_in[1];
    const void*  bat      = d_in[2];
    const float* W_conv   = (const float*)d_in[3];
    const float* b_conv   = (const float*)d_in[4];
    const float* bn_gamma = (const float*)d_in[5];
    const float* bn_beta  = (const float*)d_in[6];
    const float* bn_mean  = (const float*)d_in[7];
    const float* bn_var   = (const float*)d_in[8];
    const float* W_fc1    = (const float*)d_in[9];
    const float* b_fc1    = (const float*)d_in[10];
    const float* W_fc2    = (const float*)d_in[11];
    const float* b_fc2    = (const float*)d_in[12];
    float* out = (float*)d_out;

    k_init<<<(N_NODES + 255) / 256, 256>>>((const int*)ei, W_conv, b_conv,
                                           bn_gamma, bn_beta, bn_mean, bn_var);
    k_edge<<<(E_EDGES + 255) / 256, 256>>>(ei);
    k_scan1<<<NB_SCAN, 256>>>();
    k_scan3<<<NB_SCAN, 256>>>();
    k_place<<<(E_EDGES + 255) / 256, 256>>>(ei, bat);

    for (int l = 0; l < 3; l++) {
        k_gemm<<<(N_NODES + 63) / 64, 256>>>(x, l - 1, l);
        k_aggr<<<(N_NODES * 32 + 255) / 256, 256>>>(l);
    }

    dim3 pg(GG, 3, POOL_SPLIT);
    k_pool<<<pg, 128>>>();
    k_head<<<GG, 128>>>(W_fc1, b_fc1, W_fc2, b_fc2, out);
}

// round 16
// speedup vs baseline: 1.1559x; 1.1559x over previous
#include <cuda_runtime.h>
#include <cuda_fp16.h>
#include <cuda_fp8.h>
#include <cstdint>

#define N_NODES 100000
#define E_EDGES 3200000
#define HIDF    128
#define GG      64
#define BN_EPS  1e-5f
#define NB_SCAN 391   // ceil(N_NODES/256)
#define TSCALE  16.0f
#define INV_TSCALE (1.0f / 16.0f)
#define POOL_SPLIT 8

// ---------------- static device scratch (no runtime allocations) -------------
__device__ float g_dis[N_NODES];
__device__ int   g_hist[N_NODES];
__device__ int   g_off[N_NODES];
__device__ int   g_cursor[N_NODES];
__device__ int   g_bsum[512];
__device__ int   g_sidx[E_EDGES];
__device__ __align__(16) unsigned g_xf8[((size_t)N_NODES + 1) * 32]; // fp8 table + zero dummy row
__device__ __align__(16) __half g_hbuf[3u * N_NODES * HIDF];
__device__ __align__(16) __half g_Wh[3 * 2 * 64 * 64];
__device__ __align__(16) float g_bp[3 * HIDF];
__device__ float g_pooled[GG * 3 * HIDF];
__device__ int   g_start[GG];

static __device__ __forceinline__ __half2 fp8x2_to_h2(unsigned short v) {
    __half2_raw hr = __nv_cvt_fp8x2_to_halfraw2((__nv_fp8x2_storage_t)v, __NV_E4M3);
    return *reinterpret_cast<__half2*>(&hr);
}
static __device__ __forceinline__ unsigned short f2_to_fp8x2(float a, float b) {
    return (unsigned short)__nv_cvt_float2_to_fp8x2(make_float2(a, b), __NV_SATFINITE, __NV_E4M3);
}
// int64-vs-int32 detection on EDGE data only (values random in [0,1e5): odd
// 32-bit words all-zero iff int64). NEVER use on sorted/degenerate buffers
// like `batch` (leading zeros false-positive as int64 -> OOB; R15 bug).
static __device__ __forceinline__ int detect64(const int* p32) {
    int odd_zero = 1;
#pragma unroll 8
    for (int k = 0; k < 64; k++)
        if (p32[2 * k + 1] != 0) odd_zero = 0;
    return odd_zero;
}

// ---------------- init: hist zero + BN fold + pooled zero + dummy row --------
__global__ void k_init(const float* __restrict__ W, const float* __restrict__ b,
                       const float* __restrict__ gamma, const float* __restrict__ beta,
                       const float* __restrict__ mean, const float* __restrict__ var) {
    int i = blockIdx.x * blockDim.x + threadIdx.x;
    if (i < N_NODES) g_hist[i] = 0;
    if (i < GG * 3 * HIDF) g_pooled[i] = 0.f;
    if (i < 32) g_xf8[(size_t)N_NODES * 32 + i] = 0u;
    if (i < 3 * 8192) {
        int l = i / 8192;
        int rem = i - l * 8192;
        int p = rem / 4096;
        int j = rem & 63;
        int c = p * 64 + j;
        float sg = gamma[l * HIDF + c] * rsqrtf(var[l * HIDF + c] + BN_EPS);
        g_Wh[i] = __float2half(W[i] * sg);
    }
    if (i < 3 * HIDF) {
        float sg = gamma[i] * rsqrtf(var[i] + BN_EPS);
        g_bp[i] = b[i] * sg + (beta[i] - mean[i] * sg);
    }
}

// ---------------- edge histogram ---------------------------------------------
__global__ void k_edge(const void* __restrict__ eiv) {
    __shared__ int s64;
    if (threadIdx.x == 0) s64 = detect64((const int*)eiv);
    __syncthreads();
    int e = blockIdx.x * blockDim.x + threadIdx.x;
    if (e >= E_EDGES) return;
    int c;
    if (s64) c = (int)((const long long*)eiv)[(size_t)E_EDGES + e];
    else     c = ((const int*)eiv)[E_EDGES + e];
    atomicAdd(&g_hist[c], 1);
}

// ---------------- scan level 1 (+ dis = rsqrt(deg+1)) ------------------------
__global__ void __launch_bounds__(256) k_scan1() {
    __shared__ int sh[256];
    int bidx = blockIdx.x, t = threadIdx.x;
    int i = bidx * 256 + t;
    int v = (i < N_NODES) ? g_hist[i] : 0;
    if (i < N_NODES) g_dis[i] = rsqrtf((float)(v + 1));
    sh[t] = v;
    __syncthreads();
    for (int o = 1; o < 256; o <<= 1) {
        int u = (t >= o) ? sh[t - o] : 0;
        __syncthreads();
        sh[t] += u;
        __syncthreads();
    }
    if (i < N_NODES) g_off[i] = sh[t] - v;
    if (t == 255) g_bsum[bidx] = sh[255];
}

// ---------------- scan level 2+3 fused: per-block prefix of bsum -------------
__global__ void __launch_bounds__(256) k_scan3() {
    __shared__ int sh[256];
    int bidx = blockIdx.x, t = threadIdx.x;
    int part = 0;
    for (int k = t; k < NB_SCAN; k += 256)
        if (k < bidx) part += g_bsum[k];
    sh[t] = part;
    __syncthreads();
    for (int o = 128; o > 0; o >>= 1) {
        if (t < o) sh[t] += sh[t + o];
        __syncthreads();
    }
    int boff = sh[0];
    int i = bidx * 256 + t;
    if (i < N_NODES) {
        int o = g_off[i] + boff;
        g_off[i] = o;
        g_cursor[i] = o;
    }
}

// ---------------- place src indices (+ batch boundary detect) ----------------
// dtype detected from EDGE buffer; the same flag governs the batch reads
// (edge_index and batch share one integer dtype in this problem).
__global__ void k_place(const void* __restrict__ eiv, const void* __restrict__ bv) {
    __shared__ int s64;
    if (threadIdx.x == 0) s64 = detect64((const int*)eiv);
    __syncthreads();
    int e = blockIdx.x * blockDim.x + threadIdx.x;
    if (e < N_NODES) {
        int b, bp = -1;
        if (s64) {
            const long long* bb = (const long long*)bv;
            b = (int)bb[e];
            if (e > 0) bp = (int)bb[e - 1];
        } else {
            const int* bb = (const int*)bv;
            b = bb[e];
            if (e > 0) bp = bb[e - 1];
        }
        b &= (GG - 1);                       // hard safety clamp
        if (e == 0 || bp != b) g_start[b] = e;
    }
    if (e >= E_EDGES) return;
    int r, c;
    if (s64) {
        const long long* ei = (const long long*)eiv;
        r = (int)ei[e];
        c = (int)ei[(size_t)E_EDGES + e];
    } else {
        const int* ei = (const int*)eiv;
        r = ei[e];
        c = ei[E_EDGES + e];
    }
    int pos = atomicAdd(&g_cursor[c], 1);
    g_sidx[pos] = r;
}

// ---------------- tensor-core block-diagonal GEMM -> fp8 table ---------------
#define SA_LD 136
#define SB_LD 72
__global__ void __launch_bounds__(256) k_gemm(const float* __restrict__ x,
                                              int src_layer, int layer) {
    __shared__ __half sA[64 * SA_LD];
    __shared__ __half sB[2 * 64 * SB_LD];
    int t = threadIdx.x;
    int R0 = blockIdx.x * 64;

    const __half* Wl = g_Wh + layer * 8192;
    for (int i = t; i < 8192; i += 256) {
        int p = i >> 12, k = (i >> 6) & 63, j = i & 63;
        sB[(p * 64 + k) * SB_LD + j] = Wl[i];
    }
    if (src_layer < 0) {
        for (int i = t; i < 2048; i += 256) {
            int r = i >> 5, c4 = i & 31;
            float4 v = make_float4(0.f, 0.f, 0.f, 0.f);
            if (R0 + r < N_NODES) v = ((const float4*)x)[(size_t)(R0 + r) * 32 + c4];
            __half* dst = sA + r * SA_LD + c4 * 4;
            dst[0] = __float2half(v.x); dst[1] = __float2half(v.y);
            dst[2] = __float2half(v.z); dst[3] = __float2half(v.w);
        }
    } else {
        const uint2* hb = reinterpret_cast<const uint2*>(
            g_hbuf + (size_t)src_layer * N_NODES * HIDF);
        const __half2 z2 = __floats2half2_rn(0.f, 0.f);
        for (int i = t; i < 2048; i += 256) {
            int r = i >> 5, c4 = i & 31;
            __half2 h0 = z2, h1 = z2;
            if (R0 + r < N_NODES) {
                uint2 hw = hb[(size_t)(R0 + r) * 32 + c4];
                h0 = __hmax2(*reinterpret_cast<__half2*>(&hw.x), z2);
                h1 = __hmax2(*reinterpret_cast<__half2*>(&hw.y), z2);
            }
            __half* dst = sA + r * SA_LD + c4 * 4;
            *reinterpret_cast<__half2*>(dst) = h0;
            *reinterpret_cast<__half2*>(dst + 2) = h1;
        }
    }
    __syncthreads();

    int w = t >> 5, lane = t & 31;
    int part = w & 1;
    int wr = (w >> 1) << 4;
    int g = lane >> 2, tig = lane & 3;

    float d[8][4];
#pragma unroll
    for (int n = 0; n < 8; n++) { d[n][0] = d[n][1] = d[n][2] = d[n][3] = 0.f; }

    int mrow = lane & 7;
    int msel = lane >> 3;
    int arow = wr + mrow + ((msel & 1) << 3);
    int acolb = part * 64 + ((msel >> 1) << 3);
    int brow_l = lane & 15;

#pragma unroll
    for (int kt = 0; kt < 4; kt++) {
        uint32_t a0, a1, a2, a3;
        uint32_t aaddr = (uint32_t)__cvta_generic_to_shared(
            sA + arow * SA_LD + acolb + kt * 16);
        asm volatile("ldmatrix.sync.aligned.m8n8.x4.shared.b16 {%0,%1,%2,%3}, [%4];"
                     : "=r"(a0), "=r"(a1), "=r"(a2), "=r"(a3) : "r"(aaddr));
#pragma unroll
        for (int nt = 0; nt < 8; nt++) {
            uint32_t b0, b1;
            uint32_t baddr = (uint32_t)__cvta_generic_to_shared(
                sB + (part * 64 + kt * 16 + brow_l) * SB_LD + nt * 8);
            asm volatile("ldmatrix.sync.aligned.m8n8.x2.trans.shared.b16 {%0,%1}, [%2];"
                         : "=r"(b0), "=r"(b1) : "r"(baddr));
            asm volatile("mma.sync.aligned.m16n8k16.row.col.f32.f16.f16.f32 "
                         "{%0,%1,%2,%3}, {%4,%5,%6,%7}, {%8,%9}, {%0,%1,%2,%3};"
                         : "+f"(d[nt][0]), "+f"(d[nt][1]), "+f"(d[nt][2]), "+f"(d[nt][3])
                         : "r"(a0), "r"(a1), "r"(a2), "r"(a3), "r"(b0), "r"(b1));
        }
    }

    int row0 = R0 + wr + g;
    int row1 = row0 + 8;
    unsigned short* xf16 = reinterpret_cast<unsigned short*>(g_xf8);
    if (row0 < N_NODES) {
        float sc = TSCALE * g_dis[row0];
#pragma unroll
        for (int nt = 0; nt < 8; nt++) {
            int cidx = part * 32 + nt * 4 + tig;
            xf16[(size_t)row0 * 64 + cidx] = f2_to_fp8x2(d[nt][0] * sc, d[nt][1] * sc);
        }
    }
    if (row1 < N_NODES) {
        float sc = TSCALE * g_dis[row1];
#pragma unroll
        for (int nt = 0; nt < 8; nt++) {
            int cidx = part * 32 + nt * 4 + tig;
            xf16[(size_t)row1 * 64 + cidx] = f2_to_fp8x2(d[nt][2] * sc, d[nt][3] * sc);
        }
    }
}

// ---------------- segmented sum: one warp per node, 2 edges/iter (R12) -------
__global__ void __launch_bounds__(256) k_aggr(int layer) {
    int node = (blockIdx.x * 256 + threadIdx.x) >> 5;
    if (node >= N_NODES) return;
    int lane = threadIdx.x & 31;
    int lg = lane & 15;
    int half1 = lane >> 4;
    int s0 = g_off[node];
    int s1 = (node + 1 < N_NODES) ? g_off[node + 1] : E_EDGES;

    const uint2* __restrict__ xb2 = reinterpret_cast<const uint2*>(g_xf8);
    const __half2 z2 = __floats2half2_rn(0.f, 0.f);
    __half2 a0 = z2, a1 = z2, a2 = z2, a3 = z2;

    for (int s = s0; s < s1; s += 32) {
        int idx = N_NODES;                       // zero dummy row
        if (s + lane < s1) idx = g_sidx[s + lane];
        int cnt = min(32, s1 - s);
        int jmax = (cnt + 1) >> 1;
        for (int j = 0; j < jmax; j++) {
            int r = __shfl_sync(0xffffffffu, idx, 2 * j + half1);
            uint2 w = __ldg(xb2 + (size_t)r * 16 + lg);
            a0 = __hadd2(a0, fp8x2_to_h2((unsigned short)(w.x & 0xffffu)));
            a1 = __hadd2(a1, fp8x2_to_h2((unsigned short)(w.x >> 16)));
            a2 = __hadd2(a2, fp8x2_to_h2((unsigned short)(w.y & 0xffffu)));
            a3 = __hadd2(a3, fp8x2_to_h2((unsigned short)(w.y >> 16)));
        }
    }

    a0 = __hadd2(a0, __shfl_xor_sync(0xffffffffu, a0, 16));
    a1 = __hadd2(a1, __shfl_xor_sync(0xffffffffu, a1, 16));
    a2 = __hadd2(a2, __shfl_xor_sync(0xffffffffu, a2, 16));
    a3 = __hadd2(a3, __shfl_xor_sync(0xffffffffu, a3, 16));

    if (half1 == 0) {
        uint2 sw = xb2[(size_t)node * 16 + lg];
        a0 = __hadd2(a0, fp8x2_to_h2((unsigned short)(sw.x & 0xffffu)));
        a1 = __hadd2(a1, fp8x2_to_h2((unsigned short)(sw.x >> 16)));
        a2 = __hadd2(a2, fp8x2_to_h2((unsigned short)(sw.y & 0xffffu)));
        a3 = __hadd2(a3, fp8x2_to_h2((unsigned short)(sw.y >> 16)));

        float dcs = g_dis[node] * INV_TSCALE;
        const float4* bp4 = (const float4*)g_bp;
        float4 b0 = bp4[layer * 32 + lg * 2];
        float4 b1 = bp4[layer * 32 + lg * 2 + 1];
        float2 f0 = __half22float2(a0);
        float2 f1 = __half22float2(a1);
        float2 f2 = __half22float2(a2);
        float2 f3 = __half22float2(a3);
        __half2 o0 = __floats2half2_rn(b0.x + f0.x * dcs, b0.y + f0.y * dcs);
        __half2 o1 = __floats2half2_rn(b0.z + f1.x * dcs, b0.w + f1.y * dcs);
        __half2 o2 = __floats2half2_rn(b1.x + f2.x * dcs, b1.y + f2.y * dcs);
        __half2 o3 = __floats2half2_rn(b1.z + f3.x * dcs, b1.w + f3.y * dcs);
        uint4 st;
        *reinterpret_cast<__half2*>(&st.x) = o0;
        *reinterpret_cast<__half2*>(&st.y) = o1;
        *reinterpret_cast<__half2*>(&st.z) = o2;
        *reinterpret_cast<__half2*>(&st.w) = o3;
        reinterpret_cast<uint4*>(g_hbuf + (size_t)layer * N_NODES * HIDF)
            [(size_t)node * 16 + lg] = st;
    }
}

// ---------------- mean pool: split + atomic partial sums ---------------------
__global__ void __launch_bounds__(128) k_pool() {
    int g = blockIdx.x;
    int l = blockIdx.y;
    int z = blockIdx.z;
    int t = threadIdx.x;
    int s = g_start[g];
    int e = (g < GG - 1) ? g_start[g + 1] : N_NODES;
    int n = e - s;
    int chunk = (n + POOL_SPLIT - 1) / POOL_SPLIT;
    int j0 = z * chunk;
    int j1 = min(n, j0 + chunk);
    if (j0 >= j1) return;
    const __half* base = g_hbuf + ((size_t)l * N_NODES + s) * HIDF + t;
    float acc = 0.f;
    for (int j = j0; j < j1; j++) acc += fmaxf(__half2float(base[(size_t)j * HIDF]), 0.f);
    atomicAdd(&g_pooled[g * (3 * HIDF) + l * HIDF + t], acc);
}

// ---------------- MLP head + log_softmax -------------------------------------
__global__ void __launch_bounds__(128) k_head(const float* __restrict__ Wfc1,
                                              const float* __restrict__ bfc1,
                                              const float* __restrict__ Wfc2,
                                              const float* __restrict__ bfc2,
                                              float* __restrict__ out) {
    __shared__ float sP[3 * HIDF];
    __shared__ float sH[HIDF];
    __shared__ float sZ[2];
    int g = blockIdx.x;
    int t = threadIdx.x;
    int s = g_start[g];
    int e = (g < GG - 1) ? g_start[g + 1] : N_NODES;
    float inv = 1.0f / fmaxf((float)(e - s), 1.0f);
    for (int i = t; i < 3 * HIDF; i += 128) sP[i] = g_pooled[g * (3 * HIDF) + i] * inv;
    __syncthreads();
    float acc = bfc1[t];
#pragma unroll 8
    for (int k = 0; k < 3 * HIDF; k++) acc += sP[k] * Wfc1[k * HIDF + t];
    sH[t] = fmaxf(acc, 0.f);
    __syncthreads();
    if (t < 2) {
        float z = bfc2[t];
#pragma unroll 8
        for (int j = 0; j < HIDF; j++) z += sH[j] * Wfc2[j * 2 + t];
        sZ[t] = z;
    }
    __syncthreads();
    if (t == 0) {
        float z0 = sZ[0], z1 = sZ[1];
        float m = fmaxf(z0, z1);
        float lse = m + logf(expf(z0 - m) + expf(z1 - m));
        out[g * 2 + 0] = z0 - lse;
        out[g * 2 + 1] = z1 - lse;
    }
}

// ---------------- driver ------------------------------------------------------
extern "C" void kernel_launch(void* const* d_in, const int* in_sizes, int n_in,
                              void* d_out, int out_size) {
    const float* x        = (const float*)d_in[0];
    const void*  ei       = d_in[1];
    const void*  bat      = d_in[2];
    const float* W_conv   = (const float*)d_in[3];
    const float* b_conv   = (const float*)d_in[4];
    const float* bn_gamma = (const float*)d_in[5];
    const float* bn_beta  = (const float*)d_in[6];
    const float* bn_mean  = (const float*)d_in[7];
    const float* bn_var   = (const float*)d_in[8];
    const float* W_fc1    = (const float*)d_in[9];
    const float* b_fc1    = (const float*)d_in[10];
    const float* W_fc2    = (const float*)d_in[11];
    const float* b_fc2    = (const float*)d_in[12];
    float* out = (float*)d_out;

    k_init<<<(N_NODES + 255) / 256, 256>>>(W_conv, b_conv, bn_gamma, bn_beta,
                                           bn_mean, bn_var);
    k_edge<<<(E_EDGES + 255) / 256, 256>>>(ei);
    k_scan1<<<NB_SCAN, 256>>>();
    k_scan3<<<NB_SCAN, 256>>>();
    k_place<<<(E_EDGES + 255) / 256, 256>>>(ei, bat);

    for (int l = 0; l < 3; l++) {
        k_gemm<<<(N_NODES + 63) / 64, 256>>>(x, l - 1, l);
        k_aggr<<<(N_NODES * 32 + 255) / 256, 256>>>(l);
    }

    dim3 pg(GG, 3, POOL_SPLIT);
    k_pool<<<pg, 128>>>();
    k_head<<<GG, 128>>>(W_fc1, b_fc1, W_fc2, b_fc2, out);
}

// round 17
// speedup vs baseline: 1.1831x; 1.0235x over previous
#include <cuda_runtime.h>
#include <cuda_fp16.h>
#include <cuda_fp8.h>
#include <cstdint>

#define N_NODES 100000
#define E_EDGES 3200000
#define HIDF    128
#define GG      64
#define BN_EPS  1e-5f
#define NB_SCAN 391   // ceil(N_NODES/256)
#define TSCALE  16.0f
#define INV_TSCALE (1.0f / 16.0f)
#define POOL_SPLIT 8

// ---------------- static device scratch (no runtime allocations) -------------
__device__ float g_dis[N_NODES];
__device__ int   g_hist[N_NODES];      // zero at load; self-cleaned by k_scan1
__device__ int   g_off[N_NODES];
__device__ int   g_cursor[N_NODES];
__device__ int   g_bsum[512];
__device__ int   g_sidx[E_EDGES];
__device__ __align__(16) unsigned g_xf8[((size_t)N_NODES + 1) * 32]; // fp8 table + zero dummy row
__device__ __align__(16) __half g_hbuf[3u * N_NODES * HIDF];         // post-ReLU layer outputs
__device__ __align__(16) __half g_Wh[3 * 2 * 64 * 64];
__device__ __align__(16) float g_bp[3 * HIDF];
__device__ float g_pooled[GG * 3 * HIDF];  // zero at load; self-cleaned by k_head
__device__ int   g_start[GG];

static __device__ __forceinline__ __half2 fp8x2_to_h2(unsigned short v) {
    __half2_raw hr = __nv_cvt_fp8x2_to_halfraw2((__nv_fp8x2_storage_t)v, __NV_E4M3);
    return *reinterpret_cast<__half2*>(&hr);
}
static __device__ __forceinline__ unsigned short f2_to_fp8x2(float a, float b) {
    return (unsigned short)__nv_cvt_float2_to_fp8x2(make_float2(a, b), __NV_SATFINITE, __NV_E4M3);
}
// int64-vs-int32 detection on EDGE data only (values random in [0,1e5): odd
// 32-bit words all-zero iff int64). NEVER use on sorted/degenerate buffers
// like `batch` (leading zeros false-positive as int64 -> OOB; R15 bug).
static __device__ __forceinline__ int detect64(const int* p32) {
    int odd_zero = 1;
#pragma unroll 8
    for (int k = 0; k < 64; k++)
        if (p32[2 * k + 1] != 0) odd_zero = 0;
    return odd_zero;
}

// ---------------- edge histogram + BN fold + dummy-row zero ------------------
__global__ void k_edge(const void* __restrict__ eiv,
                       const float* __restrict__ W, const float* __restrict__ b,
                       const float* __restrict__ gamma, const float* __restrict__ beta,
                       const float* __restrict__ mean, const float* __restrict__ var) {
    __shared__ int s64;
    if (threadIdx.x == 0) s64 = detect64((const int*)eiv);
    __syncthreads();
    int e = blockIdx.x * blockDim.x + threadIdx.x;
    if (e < 32) g_xf8[(size_t)N_NODES * 32 + e] = 0u;
    if (e < 3 * 8192) {
        int l = e / 8192;
        int rem = e - l * 8192;
        int p = rem / 4096;
        int j = rem & 63;
        int c = p * 64 + j;
        float sg = gamma[l * HIDF + c] * rsqrtf(var[l * HIDF + c] + BN_EPS);
        g_Wh[e] = __float2half(W[e] * sg);
    }
    if (e < 3 * HIDF) {
        float sg = gamma[e] * rsqrtf(var[e] + BN_EPS);
        g_bp[e] = b[e] * sg + (beta[e] - mean[e] * sg);
    }
    if (e >= E_EDGES) return;
    int c;
    if (s64) c = (int)((const long long*)eiv)[(size_t)E_EDGES + e];
    else     c = ((const int*)eiv)[E_EDGES + e];
    atomicAdd(&g_hist[c], 1);
}

// ---------------- scan level 1 (+ dis = rsqrt(deg+1), hist self-clean) -------
__global__ void __launch_bounds__(256) k_scan1() {
    __shared__ int sh[256];
    int bidx = blockIdx.x, t = threadIdx.x;
    int i = bidx * 256 + t;
    int v = 0;
    if (i < N_NODES) {
        v = g_hist[i];
        g_hist[i] = 0;                      // self-clean for next replay
        g_dis[i] = rsqrtf((float)(v + 1));
    }
    sh[t] = v;
    __syncthreads();
    for (int o = 1; o < 256; o <<= 1) {
        int u = (t >= o) ? sh[t - o] : 0;
        __syncthreads();
        sh[t] += u;
        __syncthreads();
    }
    if (i < N_NODES) g_off[i] = sh[t] - v;
    if (t == 255) g_bsum[bidx] = sh[255];
}

// ---------------- scan level 2+3 fused: per-block prefix of bsum -------------
__global__ void __launch_bounds__(256) k_scan3() {
    __shared__ int sh[256];
    int bidx = blockIdx.x, t = threadIdx.x;
    int part = 0;
    for (int k = t; k < NB_SCAN; k += 256)
        if (k < bidx) part += g_bsum[k];
    sh[t] = part;
    __syncthreads();
    for (int o = 128; o > 0; o >>= 1) {
        if (t < o) sh[t] += sh[t + o];
        __syncthreads();
    }
    int boff = sh[0];
    int i = bidx * 256 + t;
    if (i < N_NODES) {
        int o = g_off[i] + boff;
        g_off[i] = o;
        g_cursor[i] = o;
    }
}

// ---------------- place src indices (+ batch boundary detect) ----------------
// dtype detected from EDGE buffer; the same flag governs the batch reads.
__global__ void k_place(const void* __restrict__ eiv, const void* __restrict__ bv) {
    __shared__ int s64;
    if (threadIdx.x == 0) s64 = detect64((const int*)eiv);
    __syncthreads();
    int e = blockIdx.x * blockDim.x + threadIdx.x;
    if (e < N_NODES) {
        int b, bp = -1;
        if (s64) {
            const long long* bb = (const long long*)bv;
            b = (int)bb[e];
            if (e > 0) bp = (int)bb[e - 1];
        } else {
            const int* bb = (const int*)bv;
            b = bb[e];
            if (e > 0) bp = bb[e - 1];
        }
        b &= (GG - 1);                       // hard safety clamp
        if (e == 0 || bp != b) g_start[b] = e;
    }
    if (e >= E_EDGES) return;
    int r, c;
    if (s64) {
        const long long* ei = (const long long*)eiv;
        r = (int)ei[e];
        c = (int)ei[(size_t)E_EDGES + e];
    } else {
        const int* ei = (const int*)eiv;
        r = ei[e];
        c = ei[E_EDGES + e];
    }
    int pos = atomicAdd(&g_cursor[c], 1);
    g_sidx[pos] = r;
}

// ---------------- tensor-core block-diagonal GEMM -> fp8 table ---------------
// hbuf already stores post-ReLU values; no activation needed here.
#define SA_LD 136
#define SB_LD 72
__global__ void __launch_bounds__(256) k_gemm(const float* __restrict__ x,
                                              int src_layer, int layer) {
    __shared__ __half sA[64 * SA_LD];
    __shared__ __half sB[2 * 64 * SB_LD];
    int t = threadIdx.x;
    int R0 = blockIdx.x * 64;

    const __half* Wl = g_Wh + layer * 8192;
    for (int i = t; i < 8192; i += 256) {
        int p = i >> 12, k = (i >> 6) & 63, j = i & 63;
        sB[(p * 64 + k) * SB_LD + j] = Wl[i];
    }
    if (src_layer < 0) {
        for (int i = t; i < 2048; i += 256) {
            int r = i >> 5, c4 = i & 31;
            float4 v = make_float4(0.f, 0.f, 0.f, 0.f);
            if (R0 + r < N_NODES) v = ((const float4*)x)[(size_t)(R0 + r) * 32 + c4];
            __half* dst = sA + r * SA_LD + c4 * 4;
            dst[0] = __float2half(v.x); dst[1] = __float2half(v.y);
            dst[2] = __float2half(v.z); dst[3] = __float2half(v.w);
        }
    } else {
        const uint2* hb = reinterpret_cast<const uint2*>(
            g_hbuf + (size_t)src_layer * N_NODES * HIDF);
        for (int i = t; i < 2048; i += 256) {
            int r = i >> 5, c4 = i & 31;
            uint2 hw = make_uint2(0u, 0u);
            if (R0 + r < N_NODES) hw = hb[(size_t)(R0 + r) * 32 + c4];
            __half* dst = sA + r * SA_LD + c4 * 4;
            *reinterpret_cast<uint2*>(dst) = hw;
        }
    }
    __syncthreads();

    int w = t >> 5, lane = t & 31;
    int part = w & 1;
    int wr = (w >> 1) << 4;
    int g = lane >> 2, tig = lane & 3;

    float d[8][4];
#pragma unroll
    for (int n = 0; n < 8; n++) { d[n][0] = d[n][1] = d[n][2] = d[n][3] = 0.f; }

    int mrow = lane & 7;
    int msel = lane >> 3;
    int arow = wr + mrow + ((msel & 1) << 3);
    int acolb = part * 64 + ((msel >> 1) << 3);
    int brow_l = lane & 15;

#pragma unroll
    for (int kt = 0; kt < 4; kt++) {
        uint32_t a0, a1, a2, a3;
        uint32_t aaddr = (uint32_t)__cvta_generic_to_shared(
            sA + arow * SA_LD + acolb + kt * 16);
        asm volatile("ldmatrix.sync.aligned.m8n8.x4.shared.b16 {%0,%1,%2,%3}, [%4];"
                     : "=r"(a0), "=r"(a1), "=r"(a2), "=r"(a3) : "r"(aaddr));
#pragma unroll
        for (int nt = 0; nt < 8; nt++) {
            uint32_t b0, b1;
            uint32_t baddr = (uint32_t)__cvta_generic_to_shared(
                sB + (part * 64 + kt * 16 + brow_l) * SB_LD + nt * 8);
            asm volatile("ldmatrix.sync.aligned.m8n8.x2.trans.shared.b16 {%0,%1}, [%2];"
                         : "=r"(b0), "=r"(b1) : "r"(baddr));
            asm volatile("mma.sync.aligned.m16n8k16.row.col.f32.f16.f16.f32 "
                         "{%0,%1,%2,%3}, {%4,%5,%6,%7}, {%8,%9}, {%0,%1,%2,%3};"
                         : "+f"(d[nt][0]), "+f"(d[nt][1]), "+f"(d[nt][2]), "+f"(d[nt][3])
                         : "r"(a0), "r"(a1), "r"(a2), "r"(a3), "r"(b0), "r"(b1));
        }
    }

    int row0 = R0 + wr + g;
    int row1 = row0 + 8;
    unsigned short* xf16 = reinterpret_cast<unsigned short*>(g_xf8);
    if (row0 < N_NODES) {
        float sc = TSCALE * g_dis[row0];
#pragma unroll
        for (int nt = 0; nt < 8; nt++) {
            int cidx = part * 32 + nt * 4 + tig;
            xf16[(size_t)row0 * 64 + cidx] = f2_to_fp8x2(d[nt][0] * sc, d[nt][1] * sc);
        }
    }
    if (row1 < N_NODES) {
        float sc = TSCALE * g_dis[row1];
#pragma unroll
        for (int nt = 0; nt < 8; nt++) {
            int cidx = part * 32 + nt * 4 + tig;
            xf16[(size_t)row1 * 64 + cidx] = f2_to_fp8x2(d[nt][2] * sc, d[nt][3] * sc);
        }
    }
}

// ---------------- segmented sum: one warp per node, 2 edges/iter -------------
// Stores post-ReLU fp16 (both consumers use ReLU'd values).
__global__ void __launch_bounds__(256) k_aggr(int layer) {
    int node = (blockIdx.x * 256 + threadIdx.x) >> 5;
    if (node >= N_NODES) return;
    int lane = threadIdx.x & 31;
    int lg = lane & 15;
    int half1 = lane >> 4;
    int s0 = g_off[node];
    int s1 = (node + 1 < N_NODES) ? g_off[node + 1] : E_EDGES;

    const uint2* __restrict__ xb2 = reinterpret_cast<const uint2*>(g_xf8);
    const __half2 z2 = __floats2half2_rn(0.f, 0.f);
    __half2 a0 = z2, a1 = z2, a2 = z2, a3 = z2;

    for (int s = s0; s < s1; s += 32) {
        int idx = N_NODES;                       // zero dummy row
        if (s + lane < s1) idx = g_sidx[s + lane];
        int cnt = min(32, s1 - s);
        int jmax = (cnt + 1) >> 1;
        for (int j = 0; j < jmax; j++) {
            int r = __shfl_sync(0xffffffffu, idx, 2 * j + half1);
            uint2 w = __ldg(xb2 + (size_t)r * 16 + lg);
            a0 = __hadd2(a0, fp8x2_to_h2((unsigned short)(w.x & 0xffffu)));
            a1 = __hadd2(a1, fp8x2_to_h2((unsigned short)(w.x >> 16)));
            a2 = __hadd2(a2, fp8x2_to_h2((unsigned short)(w.y & 0xffffu)));
            a3 = __hadd2(a3, fp8x2_to_h2((unsigned short)(w.y >> 16)));
        }
    }

    a0 = __hadd2(a0, __shfl_xor_sync(0xffffffffu, a0, 16));
    a1 = __hadd2(a1, __shfl_xor_sync(0xffffffffu, a1, 16));
    a2 = __hadd2(a2, __shfl_xor_sync(0xffffffffu, a2, 16));
    a3 = __hadd2(a3, __shfl_xor_sync(0xffffffffu, a3, 16));

    if (half1 == 0) {
        uint2 sw = xb2[(size_t)node * 16 + lg];
        a0 = __hadd2(a0, fp8x2_to_h2((unsigned short)(sw.x & 0xffffu)));
        a1 = __hadd2(a1, fp8x2_to_h2((unsigned short)(sw.x >> 16)));
        a2 = __hadd2(a2, fp8x2_to_h2((unsigned short)(sw.y & 0xffffu)));
        a3 = __hadd2(a3, fp8x2_to_h2((unsigned short)(sw.y >> 16)));

        float dcs = g_dis[node] * INV_TSCALE;
        const float4* bp4 = (const float4*)g_bp;
        float4 b0 = bp4[layer * 32 + lg * 2];
        float4 b1 = bp4[layer * 32 + lg * 2 + 1];
        float2 f0 = __half22float2(a0);
        float2 f1 = __half22float2(a1);
        float2 f2 = __half22float2(a2);
        float2 f3 = __half22float2(a3);
        // ReLU applied at store
        __half2 o0 = __floats2half2_rn(fmaxf(b0.x + f0.x * dcs, 0.f), fmaxf(b0.y + f0.y * dcs, 0.f));
        __half2 o1 = __floats2half2_rn(fmaxf(b0.z + f1.x * dcs, 0.f), fmaxf(b0.w + f1.y * dcs, 0.f));
        __half2 o2 = __floats2half2_rn(fmaxf(b1.x + f2.x * dcs, 0.f), fmaxf(b1.y + f2.y * dcs, 0.f));
        __half2 o3 = __floats2half2_rn(fmaxf(b1.z + f3.x * dcs, 0.f), fmaxf(b1.w + f3.y * dcs, 0.f));
        uint4 st;
        *reinterpret_cast<__half2*>(&st.x) = o0;
        *reinterpret_cast<__half2*>(&st.y) = o1;
        *reinterpret_cast<__half2*>(&st.z) = o2;
        *reinterpret_cast<__half2*>(&st.w) = o3;
        reinterpret_cast<uint4*>(g_hbuf + (size_t)layer * N_NODES * HIDF)
            [(size_t)node * 16 + lg] = st;
    }
}

// ---------------- mean pool: split + atomic partial sums (inputs ReLU'd) -----
__global__ void __launch_bounds__(128) k_pool() {
    int g = blockIdx.x;
    int l = blockIdx.y;
    int z = blockIdx.z;
    int t = threadIdx.x;
    int s = g_start[g];
    int e = (g < GG - 1) ? g_start[g + 1] : N_NODES;
    int n = e - s;
    int chunk = (n + POOL_SPLIT - 1) / POOL_SPLIT;
    int j0 = z * chunk;
    int j1 = min(n, j0 + chunk);
    if (j0 >= j1) return;
    const __half* base = g_hbuf + ((size_t)l * N_NODES + s) * HIDF + t;
    float acc = 0.f;
    for (int j = j0; j < j1; j++) acc += __half2float(base[(size_t)j * HIDF]);
    atomicAdd(&g_pooled[g * (3 * HIDF) + l * HIDF + t], acc);
}

// ---------------- MLP head + log_softmax (self-cleans pooled) ----------------
__global__ void __launch_bounds__(128) k_head(const float* __restrict__ Wfc1,
                                              const float* __restrict__ bfc1,
                                              const float* __restrict__ Wfc2,
                                              const float* __restrict__ bfc2,
                                              float* __restrict__ out) {
    __shared__ float sP[3 * HIDF];
    __shared__ float sH[HIDF];
    __shared__ float sZ[2];
    int g = blockIdx.x;
    int t = threadIdx.x;
    int s = g_start[g];
    int e = (g < GG - 1) ? g_start[g + 1] : N_NODES;
    float inv = 1.0f / fmaxf((float)(e - s), 1.0f);
    for (int i = t; i < 3 * HIDF; i += 128) {
        sP[i] = g_pooled[g * (3 * HIDF) + i] * inv;
        g_pooled[g * (3 * HIDF) + i] = 0.f;    // self-clean for next replay
    }
    __syncthreads();
    float acc = bfc1[t];
#pragma unroll 8
    for (int k = 0; k < 3 * HIDF; k++) acc += sP[k] * Wfc1[k * HIDF + t];
    sH[t] = fmaxf(acc, 0.f);
    __syncthreads();
    if (t < 2) {
        float z = bfc2[t];
#pragma unroll 8
        for (int j = 0; j < HIDF; j++) z += sH[j] * Wfc2[j * 2 + t];
        sZ[t] = z;
    }
    __syncthreads();
    if (t == 0) {
        float z0 = sZ[0], z1 = sZ[1];
        float m = fmaxf(z0, z1);
        float lse = m + logf(expf(z0 - m) + expf(z1 - m));
        out[g * 2 + 0] = z0 - lse;
        out[g * 2 + 1] = z1 - lse;
    }
}

// ---------------- driver ------------------------------------------------------
extern "C" void kernel_launch(void* const* d_in, const int* in_sizes, int n_in,
                              void* d_out, int out_size) {
    const float* x        = (const float*)d_in[0];
    const void*  ei       = d_in[1];
    const void*  bat      = d_in[2];
    const float* W_conv   = (const float*)d_in[3];
    const float* b_conv   = (const float*)d_in[4];
    const float* bn_gamma = (const float*)d_in[5];
    const float* bn_beta  = (const float*)d_in[6];
    const float* bn_mean  = (const float*)d_in[7];
    const float* bn_var   = (const float*)d_in[8];
    const float* W_fc1    = (const float*)d_in[9];
    const float* b_fc1    = (const float*)d_in[10];
    const float* W_fc2    = (const float*)d_in[11];
    const float* b_fc2    = (const float*)d_in[12];
    float* out = (float*)d_out;

    k_edge<<<(E_EDGES + 255) / 256, 256>>>(ei, W_conv, b_conv, bn_gamma, bn_beta,
                                           bn_mean, bn_var);
    k_scan1<<<NB_SCAN, 256>>>();
    k_scan3<<<NB_SCAN, 256>>>();
    k_place<<<(E_EDGES + 255) / 256, 256>>>(ei, bat);

    for (int l = 0; l < 3; l++) {
        k_gemm<<<(N_NODES + 63) / 64, 256>>>(x, l - 1, l);
        k_aggr<<<(N_NODES * 32 + 255) / 256, 256>>>(l);
    }

    dim3 pg(GG, 3, POOL_SPLIT);
    k_pool<<<pg, 128>>>();
    k_head<<<GG, 128>>>(W_fc1, b_fc1, W_fc2, b_fc2, out);
}